// round 1
// baseline (speedup 1.0000x reference)
#include <cuda_runtime.h>
#include <math.h>

#define B 32
#define NTOK 4096
#define DF 768
#define KS 8
#define DS 256
#define DH 256
#define NITER 3
#define EPSV 1e-8f
#define LNEPS 1e-5f
#define ATT_SCALE 0.0625f   // 256^-0.5

// ---------------- scratch (device globals; no allocation allowed) ----------
__device__ __align__(16) float d_stats[B * NTOK * 2];         // mean, rstd per feature row
__device__ __align__(16) float d_kf[(long)B * NTOK * DH];     // 134 MB
__device__ __align__(16) float d_vf[(long)B * NTOK * DS];     // 134 MB
__device__ __align__(16) float d_Wg[(DH + DS) * DF];          // [Wk;Wv] * g_in
__device__ __align__(16) float d_wgsum[DH + DS];
__device__ __align__(16) float d_wb[DH + DS];
__device__ __align__(16) float d_slots[B * KS * DS];
__device__ __align__(16) float d_q[B * KS * DH];
__device__ __align__(16) float d_U[B * KS * DS];
__device__ __align__(16) float d_S[B * KS];
__device__ __align__(16) float d_msum[B * KS];

// ---------------- kernel 1: fold LN gain into combined weight --------------
__global__ void prep_weights(const float* __restrict__ Wk, const float* __restrict__ Wv,
                             const float* __restrict__ g_in, const float* __restrict__ b_in) {
    int j = blockIdx.x;            // 0..511
    int t = threadIdx.x;           // 256 threads
    const float* wrow = (j < DH) ? (Wk + (long)j * DF) : (Wv + (long)(j - DH) * DF);
    float sg = 0.f, sb = 0.f;
    for (int d = t; d < DF; d += 256) {
        float w = wrow[d];
        float g = g_in[d];
        d_Wg[(long)j * DF + d] = w * g;
        sg += w * g;
        sb += w * b_in[d];
    }
    __shared__ float red[64];
#pragma unroll
    for (int o = 16; o; o >>= 1) {
        sg += __shfl_xor_sync(~0u, sg, o);
        sb += __shfl_xor_sync(~0u, sb, o);
    }
    int w = t >> 5, l = t & 31;
    if (l == 0) { red[w] = sg; red[32 + w] = sb; }
    __syncthreads();
    if (t == 0) {
        float a = 0.f, c = 0.f;
        for (int i = 0; i < 8; i++) { a += red[i]; c += red[32 + i]; }
        d_wgsum[j] = a;
        d_wb[j] = c;
    }
}

// ---------------- kernel 2: per-row mean / rstd of features ----------------
__global__ void row_stats(const float* __restrict__ feat) {
    int w = threadIdx.x >> 5, l = threadIdx.x & 31;
    long row = (long)blockIdx.x * 8 + w;        // B*NTOK rows
    const float4* x = (const float4*)(feat + row * DF);
    float s = 0.f, s2 = 0.f;
#pragma unroll
    for (int i = 0; i < 6; i++) {               // 768/4/32 = 6 float4 per lane
        float4 v = x[l + 32 * i];
        s  += v.x + v.y + v.z + v.w;
        s2 += v.x * v.x + v.y * v.y + v.z * v.z + v.w * v.w;
    }
#pragma unroll
    for (int o = 16; o; o >>= 1) {
        s  += __shfl_xor_sync(~0u, s, o);
        s2 += __shfl_xor_sync(~0u, s2, o);
    }
    if (l == 0) {
        float m = s * (1.f / DF);
        float var = s2 * (1.f / DF) - m * m;
        d_stats[2 * row]     = m;
        d_stats[2 * row + 1] = rsqrtf(var + LNEPS);
    }
}

// ---------------- kernel 3: fused LN + K/V projection GEMM -----------------
// C(131072 x 512) = X @ Wg^T ; epilogue applies rstd/mean/wb correction.
#define BM 128
#define BN 64
#define BK 16
__global__ __launch_bounds__(256) void kv_gemm(const float* __restrict__ X) {
    __shared__ float As[BK][BM];
    __shared__ float Bs[BK][BN];
    int tid = threadIdx.x;
    int tx = tid & 15, ty = tid >> 4;
    long row0 = (long)blockIdx.x * BM;
    int col0 = blockIdx.y * BN;

    float acc[8][4];
#pragma unroll
    for (int i = 0; i < 8; i++)
#pragma unroll
        for (int j = 0; j < 4; j++) acc[i][j] = 0.f;

    int am = tid >> 1;
    int akk = (tid & 1) * 8;
    int bj = tid >> 2;
    int bkk = (tid & 3) * 4;

    for (int k0 = 0; k0 < DF; k0 += BK) {
        {   // A tile: row am, cols [akk, akk+8)
            const float4* src = (const float4*)(X + (row0 + am) * DF + k0 + akk);
            float4 a0 = src[0], a1 = src[1];
            As[akk + 0][am] = a0.x; As[akk + 1][am] = a0.y;
            As[akk + 2][am] = a0.z; As[akk + 3][am] = a0.w;
            As[akk + 4][am] = a1.x; As[akk + 5][am] = a1.y;
            As[akk + 6][am] = a1.z; As[akk + 7][am] = a1.w;
        }
        {   // B tile
            float4 b0 = *(const float4*)(d_Wg + (long)(col0 + bj) * DF + k0 + bkk);
            Bs[bkk + 0][bj] = b0.x; Bs[bkk + 1][bj] = b0.y;
            Bs[bkk + 2][bj] = b0.z; Bs[bkk + 3][bj] = b0.w;
        }
        __syncthreads();
#pragma unroll
        for (int kk = 0; kk < BK; kk++) {
            float a[8], bb[4];
#pragma unroll
            for (int i = 0; i < 8; i++) a[i] = As[kk][ty * 8 + i];
#pragma unroll
            for (int j = 0; j < 4; j++) bb[j] = Bs[kk][tx * 4 + j];
#pragma unroll
            for (int i = 0; i < 8; i++)
#pragma unroll
                for (int j = 0; j < 4; j++) acc[i][j] = fmaf(a[i], bb[j], acc[i][j]);
        }
        __syncthreads();
    }

    // epilogue
    bool isK = (col0 < DH);
    float* outB = isK ? d_kf : d_vf;
    int cj = (isK ? col0 : col0 - DH) + tx * 4;
    float wgs[4], wbv[4];
#pragma unroll
    for (int j = 0; j < 4; j++) {
        wgs[j] = d_wgsum[col0 + tx * 4 + j];
        wbv[j] = d_wb[col0 + tx * 4 + j];
    }
#pragma unroll
    for (int i = 0; i < 8; i++) {
        long row = row0 + ty * 8 + i;
        float m = d_stats[2 * row];
        float r = d_stats[2 * row + 1];
        float4 o;
        o.x = r * (acc[i][0] - m * wgs[0]) + wbv[0];
        o.y = r * (acc[i][1] - m * wgs[1]) + wbv[1];
        o.z = r * (acc[i][2] - m * wgs[2]) + wbv[2];
        o.w = r * (acc[i][3] - m * wgs[3]) + wbv[3];
        *(float4*)(outB + row * 256 + cj) = o;
    }
}

// ---------------- kernel 4: copy prev_slots into working slots -------------
__global__ void copy_slots(const float* __restrict__ prev) {
    int i = blockIdx.x * 256 + threadIdx.x;
    d_slots[i] = prev[i];
}

// ---------------- kernel 5: zero accumulators ------------------------------
__global__ void zero_acc() {
    int i = blockIdx.x * 256 + threadIdx.x;
    d_U[i] = 0.f;
    if (i < B * KS) { d_S[i] = 0.f; d_msum[i] = 0.f; }
}

// ---------------- kernel 6: q = LN(slots) @ Wq^T ---------------------------
__global__ __launch_bounds__(256) void slot_q(const float* __restrict__ g_s,
                                              const float* __restrict__ b_s,
                                              const float* __restrict__ Wq) {
    int bk = blockIdx.x;
    int t = threadIdx.x;
    __shared__ float sn[DS];
    __shared__ float red[16];
    float x = d_slots[bk * DS + t];
    float s = x, s2 = x * x;
#pragma unroll
    for (int o = 16; o; o >>= 1) {
        s  += __shfl_xor_sync(~0u, s, o);
        s2 += __shfl_xor_sync(~0u, s2, o);
    }
    int w = t >> 5, l = t & 31;
    if (l == 0) { red[w] = s; red[8 + w] = s2; }
    __syncthreads();
    float ms = 0.f, q2 = 0.f;
    for (int i = 0; i < 8; i++) { ms += red[i]; q2 += red[8 + i]; }
    ms *= (1.f / DS);
    float var = q2 * (1.f / DS) - ms * ms;
    float rs = rsqrtf(var + LNEPS);
    sn[t] = (x - ms) * rs * g_s[t] + b_s[t];
    __syncthreads();
    const float4* w4 = (const float4*)(Wq + (long)t * DS);
    const float4* s4 = (const float4*)sn;
    float acc = 0.f;
#pragma unroll 8
    for (int i = 0; i < 64; i++) {
        float4 a = w4[i], c = s4[i];
        acc += a.x * c.x + a.y * c.y + a.z * c.z + a.w * c.w;
    }
    d_q[bk * DH + t] = acc;
}

// ---------------- kernel 7: attention + unnormalized update accumulation ---
__global__ __launch_bounds__(256) void attn_iter() {
    int b = blockIdx.y;
    int n0 = blockIdx.x * 256;
    int t = threadIdx.x, w = t >> 5, l = t & 31;
    __shared__ float qs[KS][DS];
#pragma unroll
    for (int k = 0; k < KS; k++) qs[k][t] = d_q[(b * KS + k) * DH + t];
    __syncthreads();

    float accU[KS][8];
    float sacc[KS];
#pragma unroll
    for (int k = 0; k < KS; k++) {
        sacc[k] = 0.f;
#pragma unroll
        for (int i = 0; i < 8; i++) accU[k][i] = 0.f;
    }

    for (int ni = 0; ni < 32; ni++) {
        int n = n0 + w * 32 + ni;
        long base = ((long)b * NTOK + n) * DH;
        float kf[8];
#pragma unroll
        for (int i = 0; i < 8; i++) kf[i] = d_kf[base + i * 32 + l];
        float lg[KS];
#pragma unroll
        for (int k = 0; k < KS; k++) lg[k] = 0.f;
#pragma unroll
        for (int i = 0; i < 8; i++) {
            float kv = kf[i];
            int d = i * 32 + l;
#pragma unroll
            for (int k = 0; k < KS; k++) lg[k] = fmaf(qs[k][d], kv, lg[k]);
        }
#pragma unroll
        for (int o = 16; o; o >>= 1)
#pragma unroll
            for (int k = 0; k < KS; k++) lg[k] += __shfl_xor_sync(~0u, lg[k], o);
#pragma unroll
        for (int k = 0; k < KS; k++) lg[k] *= ATT_SCALE;
        float mx = lg[0];
#pragma unroll
        for (int k = 1; k < KS; k++) mx = fmaxf(mx, lg[k]);
        float e[KS], se = 0.f;
#pragma unroll
        for (int k = 0; k < KS; k++) { e[k] = __expf(lg[k] - mx); se += e[k]; }
        float inv = 1.f / se;
        float vf[8];
#pragma unroll
        for (int i = 0; i < 8; i++) vf[i] = d_vf[base + i * 32 + l];
#pragma unroll
        for (int k = 0; k < KS; k++) {
            float a = e[k] * inv;
            sacc[k] += a;
#pragma unroll
            for (int i = 0; i < 8; i++) accU[k][i] = fmaf(a, vf[i], accU[k][i]);
        }
    }
#pragma unroll
    for (int k = 0; k < KS; k++) {
#pragma unroll
        for (int i = 0; i < 8; i++)
            atomicAdd(&d_U[(b * KS + k) * DS + i * 32 + l], accU[k][i]);
        if (l == 0) atomicAdd(&d_S[b * KS + k], sacc[k]);
    }
}

// ---------------- kernel 8: final attention (writes attn + mask sums) ------
__global__ __launch_bounds__(256) void attn_final(float* __restrict__ attn_out) {
    int b = blockIdx.y;
    int n0 = blockIdx.x * 256;
    int t = threadIdx.x, w = t >> 5, l = t & 31;
    __shared__ float qs[KS][DS];
    __shared__ float as_[KS][256];
#pragma unroll
    for (int k = 0; k < KS; k++) qs[k][t] = d_q[(b * KS + k) * DH + t];
    __syncthreads();

    float sacc[KS];
#pragma unroll
    for (int k = 0; k < KS; k++) sacc[k] = 0.f;

    for (int ni = 0; ni < 32; ni++) {
        int nl = w * 32 + ni;
        int n = n0 + nl;
        long base = ((long)b * NTOK + n) * DH;
        float kf[8];
#pragma unroll
        for (int i = 0; i < 8; i++) kf[i] = d_kf[base + i * 32 + l];
        float lg[KS];
#pragma unroll
        for (int k = 0; k < KS; k++) lg[k] = 0.f;
#pragma unroll
        for (int i = 0; i < 8; i++) {
            float kv = kf[i];
            int d = i * 32 + l;
#pragma unroll
            for (int k = 0; k < KS; k++) lg[k] = fmaf(qs[k][d], kv, lg[k]);
        }
#pragma unroll
        for (int o = 16; o; o >>= 1)
#pragma unroll
            for (int k = 0; k < KS; k++) lg[k] += __shfl_xor_sync(~0u, lg[k], o);
#pragma unroll
        for (int k = 0; k < KS; k++) lg[k] *= ATT_SCALE;
        float mx = lg[0];
#pragma unroll
        for (int k = 1; k < KS; k++) mx = fmaxf(mx, lg[k]);
        float e[KS], se = 0.f;
#pragma unroll
        for (int k = 0; k < KS; k++) { e[k] = __expf(lg[k] - mx); se += e[k]; }
        float inv = 1.f / se;
#pragma unroll
        for (int k = 0; k < KS; k++) {
            float a = e[k] * inv;
            sacc[k] += a;
            if (l == (unsigned)k) as_[k][nl] = a;
        }
    }
    __syncthreads();
#pragma unroll
    for (int k = 0; k < KS; k++)
        attn_out[((long)(b * KS + k)) * NTOK + n0 + t] = as_[k][t];
    if (l == 0)
#pragma unroll
        for (int k = 0; k < KS; k++) atomicAdd(&d_msum[b * KS + k], sacc[k]);
}

// ---------------- kernel 9: GRU + LN + MLP slot update ---------------------
__global__ __launch_bounds__(256) void slot_update(
    const float* __restrict__ W_ih, const float* __restrict__ W_hh,
    const float* __restrict__ b_ih, const float* __restrict__ b_hh,
    const float* __restrict__ g_m, const float* __restrict__ b_m,
    const float* __restrict__ W1, const float* __restrict__ b1,
    const float* __restrict__ W2, const float* __restrict__ b2) {
    int bk = blockIdx.x;
    int t = threadIdx.x;
    __shared__ float u[DS], so[DS], h_s[DS], hn[DS], m1[DS];
    __shared__ float red[16];

    float Sv = d_S[bk] + EPSV;
    u[t]  = d_U[bk * DS + t] / Sv;
    so[t] = d_slots[bk * DS + t];
    __syncthreads();

    const float4* u4 = (const float4*)u;
    const float4* s4 = (const float4*)so;
    float gi[3], gh[3];
#pragma unroll
    for (int g = 0; g < 3; g++) {
        const float4* wi = (const float4*)(W_ih + (long)(g * DS + t) * DS);
        const float4* wh = (const float4*)(W_hh + (long)(g * DS + t) * DS);
        float ai = 0.f, ah = 0.f;
#pragma unroll 8
        for (int i = 0; i < 64; i++) {
            float4 a = wi[i], c = u4[i];
            ai += a.x * c.x + a.y * c.y + a.z * c.z + a.w * c.w;
            float4 d = wh[i], e = s4[i];
            ah += d.x * e.x + d.y * e.y + d.z * e.z + d.w * e.w;
        }
        gi[g] = ai + b_ih[g * DS + t];
        gh[g] = ah + b_hh[g * DS + t];
    }
    float r  = 1.f / (1.f + __expf(-(gi[0] + gh[0])));
    float z  = 1.f / (1.f + __expf(-(gi[1] + gh[1])));
    float nn = tanhf(gi[2] + r * gh[2]);
    float h  = (1.f - z) * nn + z * so[t];
    h_s[t] = h;

    // layernorm of h
    float s = h, s2 = h * h;
#pragma unroll
    for (int o = 16; o; o >>= 1) {
        s  += __shfl_xor_sync(~0u, s, o);
        s2 += __shfl_xor_sync(~0u, s2, o);
    }
    int w = t >> 5, l = t & 31;
    if (l == 0) { red[w] = s; red[8 + w] = s2; }
    __syncthreads();
    float ms = 0.f, q2 = 0.f;
    for (int i = 0; i < 8; i++) { ms += red[i]; q2 += red[8 + i]; }
    ms *= (1.f / DS);
    float var = q2 * (1.f / DS) - ms * ms;
    float rs = rsqrtf(var + LNEPS);
    hn[t] = (h - ms) * rs * g_m[t] + b_m[t];
    __syncthreads();

    // MLP layer 1
    {
        const float4* w1 = (const float4*)(W1 + (long)t * DS);
        const float4* x4 = (const float4*)hn;
        float a1 = 0.f;
#pragma unroll 8
        for (int i = 0; i < 64; i++) {
            float4 a = w1[i], c = x4[i];
            a1 += a.x * c.x + a.y * c.y + a.z * c.z + a.w * c.w;
        }
        m1[t] = fmaxf(a1 + b1[t], 0.f);
    }
    __syncthreads();
    // MLP layer 2 + residual
    {
        const float4* w2 = (const float4*)(W2 + (long)t * DS);
        const float4* x4 = (const float4*)m1;
        float a2 = 0.f;
#pragma unroll 8
        for (int i = 0; i < 64; i++) {
            float4 a = w2[i], c = x4[i];
            a2 += a.x * c.x + a.y * c.y + a.z * c.z + a.w * c.w;
        }
        d_slots[bk * DS + t] = h + a2 + b2[t];
    }
}

// ---------------- kernel 10: confidence blend ------------------------------
__global__ void blend(const float* __restrict__ prev, float* __restrict__ out) {
    int i = blockIdx.x * 256 + threadIdx.x;     // B*KS*DS
    int bk = i >> 8;
    float mask = 1.f / (1.f + __expf(-d_msum[bk] * (1.f / NTOK)));
    out[i] = d_slots[i] * mask + prev[i] * (1.f - mask);
}

// ---------------- launch ---------------------------------------------------
extern "C" void kernel_launch(void* const* d_in, const int* in_sizes, int n_in,
                              void* d_out, int out_size) {
    const float* features  = (const float*)d_in[0];
    const float* prev      = (const float*)d_in[1];
    const float* g_in      = (const float*)d_in[2];
    const float* b_in      = (const float*)d_in[3];
    const float* g_s       = (const float*)d_in[4];
    const float* b_s       = (const float*)d_in[5];
    const float* g_m       = (const float*)d_in[6];
    const float* b_m       = (const float*)d_in[7];
    const float* Wq        = (const float*)d_in[8];
    const float* Wk        = (const float*)d_in[9];
    const float* Wv        = (const float*)d_in[10];
    const float* W_ih      = (const float*)d_in[11];
    const float* W_hh      = (const float*)d_in[12];
    const float* b_ih      = (const float*)d_in[13];
    const float* b_hh      = (const float*)d_in[14];
    const float* W1        = (const float*)d_in[15];
    const float* b1        = (const float*)d_in[16];
    const float* W2        = (const float*)d_in[17];
    const float* b2        = (const float*)d_in[18];

    float* out      = (float*)d_out;
    float* attn_out = out + B * KS * DS;

    prep_weights<<<DH + DS, 256>>>(Wk, Wv, g_in, b_in);
    row_stats<<<B * NTOK / 8, 256>>>(features);
    kv_gemm<<<dim3(B * NTOK / BM, (DH + DS) / BN), 256>>>(features);
    copy_slots<<<B * KS * DS / 256, 256>>>(prev);

    for (int it = 0; it < NITER; it++) {
        zero_acc<<<B * KS * DS / 256, 256>>>();
        slot_q<<<B * KS, 256>>>(g_s, b_s, Wq);
        attn_iter<<<dim3(NTOK / 256, B), 256>>>();
        slot_update<<<B * KS, 256>>>(W_ih, W_hh, b_ih, b_hh, g_m, b_m, W1, b1, W2, b2);
    }
    zero_acc<<<B * KS * DS / 256, 256>>>();
    slot_q<<<B * KS, 256>>>(g_s, b_s, Wq);
    attn_final<<<dim3(NTOK / 256, B), 256>>>(attn_out);
    blend<<<B * KS * DS / 256, 256>>>(prev, out);
}

// round 3
// speedup vs baseline: 1.7695x; 1.7695x over previous
#include <cuda_runtime.h>
#include <cuda_bf16.h>
#include <math.h>
#include <stdint.h>

#define B 32
#define NTOK 4096
#define DF 768
#define KS 8
#define DS 256
#define DH 256
#define NITER 3
#define EPSV 1e-8f
#define LNEPS 1e-5f
#define ATT_SCALE 0.0625f   // 256^-0.5

// ---------------- scratch (device globals; no allocation allowed) ----------
__device__ __align__(16) float d_stats[B * NTOK * 2];
__device__ __align__(16) float d_kf[(long)B * NTOK * DH];     // 134 MB
__device__ __align__(16) float d_vf[(long)B * NTOK * DS];     // 134 MB
__device__ __align__(16) __nv_bfloat16 d_Wh[(DH + DS) * DF];  // hi(W*g)
__device__ __align__(16) __nv_bfloat16 d_Wl[(DH + DS) * DF];  // lo(W*g)
__device__ __align__(16) float d_wgsum[DH + DS];
__device__ __align__(16) float d_wb[DH + DS];
__device__ __align__(16) float d_slots[B * KS * DS];
__device__ __align__(16) float d_q[B * KS * DH];
__device__ __align__(16) float d_U[B * KS * DS];
__device__ __align__(16) float d_S[B * KS];
__device__ __align__(16) float d_msum[B * KS];

// ================= mma.sync helpers (sm_80+ baseline; OK for plain sm_103) =
__device__ __forceinline__ void ldsm4(uint32_t* r, uint32_t addr) {
    asm volatile("ldmatrix.sync.aligned.m8n8.x4.shared.b16 {%0,%1,%2,%3}, [%4];"
        : "=r"(r[0]), "=r"(r[1]), "=r"(r[2]), "=r"(r[3]) : "r"(addr));
}
__device__ __forceinline__ void mma16816(float* c, const uint32_t* a, const uint32_t* b) {
    asm volatile("mma.sync.aligned.m16n8k16.row.col.f32.bf16.bf16.f32 "
        "{%0,%1,%2,%3}, {%4,%5,%6,%7}, {%8,%9}, {%0,%1,%2,%3};"
        : "+f"(c[0]), "+f"(c[1]), "+f"(c[2]), "+f"(c[3])
        : "r"(a[0]), "r"(a[1]), "r"(a[2]), "r"(a[3]), "r"(b[0]), "r"(b[1]));
}
#define CPA(dst, src) asm volatile("cp.async.cg.shared.global [%0], [%1], 16;" :: "r"(dst), "l"(src))
#define CPC() asm volatile("cp.async.commit_group;" ::: "memory")
#define CPW1() asm volatile("cp.async.wait_group 1;" ::: "memory")
__device__ __forceinline__ uint32_t smem_u32(const void* p) {
    uint32_t a;
    asm("{ .reg .u64 t; cvta.to.shared.u64 t, %1; cvt.u32.u64 %0, t; }" : "=r"(a) : "l"(p));
    return a;
}

// ---------------- kernel 1: fold LN gain, build bf16 hi/lo weights ---------
__global__ void prep_weights(const float* __restrict__ Wk, const float* __restrict__ Wv,
                             const float* __restrict__ g_in, const float* __restrict__ b_in) {
    int j = blockIdx.x;            // 0..511
    int t = threadIdx.x;           // 256 threads
    const float* wrow = (j < DH) ? (Wk + (long)j * DF) : (Wv + (long)(j - DH) * DF);
    float sg = 0.f, sb = 0.f;
    for (int d = t; d < DF; d += 256) {
        float w = wrow[d];
        float g = g_in[d];
        float wg = w * g;
        __nv_bfloat16 hi = __float2bfloat16_rn(wg);
        d_Wh[(long)j * DF + d] = hi;
        d_Wl[(long)j * DF + d] = __float2bfloat16_rn(wg - __bfloat162float(hi));
        sg += wg;
        sb += w * b_in[d];
    }
    __shared__ float red[64];
#pragma unroll
    for (int o = 16; o; o >>= 1) {
        sg += __shfl_xor_sync(~0u, sg, o);
        sb += __shfl_xor_sync(~0u, sb, o);
    }
    int w = t >> 5, l = t & 31;
    if (l == 0) { red[w] = sg; red[32 + w] = sb; }
    __syncthreads();
    if (t == 0) {
        float a = 0.f, c = 0.f;
        for (int i = 0; i < 8; i++) { a += red[i]; c += red[32 + i]; }
        d_wgsum[j] = a;
        d_wb[j] = c;
    }
}

// ---------------- kernel 2: per-row mean / rstd of features ----------------
__global__ void row_stats(const float* __restrict__ feat) {
    int w = threadIdx.x >> 5, l = threadIdx.x & 31;
    long row = (long)blockIdx.x * 8 + w;
    const float4* x = (const float4*)(feat + row * DF);
    float s = 0.f, s2 = 0.f;
#pragma unroll
    for (int i = 0; i < 6; i++) {
        float4 v = x[l + 32 * i];
        s  += v.x + v.y + v.z + v.w;
        s2 += v.x * v.x + v.y * v.y + v.z * v.z + v.w * v.w;
    }
#pragma unroll
    for (int o = 16; o; o >>= 1) {
        s  += __shfl_xor_sync(~0u, s, o);
        s2 += __shfl_xor_sync(~0u, s2, o);
    }
    if (l == 0) {
        float m = s * (1.f / DF);
        float var = s2 * (1.f / DF) - m * m;
        d_stats[2 * row]     = m;
        d_stats[2 * row + 1] = rsqrtf(var + LNEPS);
    }
}

// ---------------- kernel 3: mma.sync bf16x3 fused LN + K/V GEMM ------------
// C(131072 x 512) = X @ Wg^T. CTA 128M x 128N, K-chunk 32, 3-stage pipeline.
// Stage: Ah | Al | Bh | Bl, each 128 rows x 80B (32 bf16 + 16B pad) = 10240B.
#define KCH 32
#define NCHUNKS 24
#define A_HI 0
#define A_LO 10240
#define B_HI 20480
#define B_LO 30720
#define STG  40960
#define SMEM_GEMM (3 * STG)

__global__ void __launch_bounds__(256, 1) kv_gemm_mma(const float* __restrict__ X) {
    extern __shared__ char sm[];
    uint32_t sb = smem_u32(sm);
    int t = threadIdx.x;
    int w = t >> 5, l = t & 31;
    int wm = w & 3, wn = w >> 2;           // 4 m-warps x 2 n-warps
    int m0 = wm * 32, n0w = wn * 64;
    int N0 = blockIdx.x * 128;             // N-tile fastest -> L2 reuse of X
    long row0 = (long)blockIdx.y * 128;

    // producer indexing
    int arow = t >> 1, ahalf = t & 1;
    const float* aptr = X + (row0 + arow) * (long)DF + ahalf * 16;
    char* a_st = sm + arow * 80 + ahalf * 32;            // + stage + A_HI/A_LO
    int bn = t >> 2, bc = t & 3;
    const __nv_bfloat16* bhs0 = d_Wh + (size_t)(N0 + bn) * DF + bc * 8;
    const __nv_bfloat16* bhs1 = d_Wh + (size_t)(N0 + 64 + bn) * DF + bc * 8;
    const __nv_bfloat16* bls0 = d_Wl + (size_t)(N0 + bn) * DF + bc * 8;
    const __nv_bfloat16* bls1 = d_Wl + (size_t)(N0 + 64 + bn) * DF + bc * 8;
    uint32_t b_st0 = sb + bn * 80 + bc * 16;             // + stage + B_HI/B_LO
    uint32_t b_st1 = sb + (64 + bn) * 80 + bc * 16;

    // consumer base addresses (lane-dependent, stage-relative)
    uint32_t aA = sb + (uint32_t)((m0 + (l & 15)) * 80 + (l >> 4) * 16);
    uint32_t aB = sb + (uint32_t)(B_HI + (n0w + (l & 7) + ((l >> 4) & 1) * 8) * 80 + ((l >> 3) & 1) * 16);

    float acc[2][8][4];
#pragma unroll
    for (int i = 0; i < 2; i++)
#pragma unroll
        for (int j = 0; j < 8; j++)
#pragma unroll
            for (int q = 0; q < 4; q++) acc[i][j][q] = 0.f;

    float4 af[4];

#define LOAD_A(c) { const float4* s4_ = (const float4*)(aptr + (c) * KCH); \
    af[0] = s4_[0]; af[1] = s4_[1]; af[2] = s4_[2]; af[3] = s4_[3]; }

#define STORE_A(soff) { \
    uint32_t H_[4], L_[4]; const float* f_ = (const float*)af; \
    _Pragma("unroll") for (int i_ = 0; i_ < 4; i_++) { \
        float a_ = f_[4*i_], b_ = f_[4*i_+1], c_ = f_[4*i_+2], d_ = f_[4*i_+3]; \
        __nv_bfloat162 hp_, lp_, hq_, lq_; \
        hp_.x = __float2bfloat16_rn(a_); hp_.y = __float2bfloat16_rn(b_); \
        lp_.x = __float2bfloat16_rn(a_ - __bfloat162float(hp_.x)); \
        lp_.y = __float2bfloat16_rn(b_ - __bfloat162float(hp_.y)); \
        hq_.x = __float2bfloat16_rn(c_); hq_.y = __float2bfloat16_rn(d_); \
        lq_.x = __float2bfloat16_rn(c_ - __bfloat162float(hq_.x)); \
        lq_.y = __float2bfloat16_rn(d_ - __bfloat162float(hq_.y)); \
        H_[i_] = (i_ & 1) ? 0 : 0; /* placeholder, overwritten below */ \
        ((uint32_t*)H_)[i_] = (*(uint32_t*)&hp_); /* 2 bf16 */ \
        ((uint32_t*)L_)[i_] = (*(uint32_t*)&lp_); \
        /* second pair goes to adjacent slot via direct store below */ \
        ((uint2*)a_st)[0] = ((uint2*)a_st)[0]; /* no-op to quiet compiler */ \
        (void)hq_; (void)lq_; \
    } }

    // NOTE: macro above is awkward; use an explicit inline block instead.
#undef STORE_A
#define STORE_A(soff) { \
    const float* f_ = (const float*)af; \
    uint32_t H_[8], L_[8]; \
    _Pragma("unroll") for (int i_ = 0; i_ < 8; i_++) { \
        float a_ = f_[2*i_], b_ = f_[2*i_+1]; \
        __nv_bfloat162 hp_, lp_; \
        hp_.x = __float2bfloat16_rn(a_); hp_.y = __float2bfloat16_rn(b_); \
        lp_.x = __float2bfloat16_rn(a_ - __bfloat162float(hp_.x)); \
        lp_.y = __float2bfloat16_rn(b_ - __bfloat162float(hp_.y)); \
        H_[i_] = *(uint32_t*)&hp_; L_[i_] = *(uint32_t*)&lp_; \
    } \
    *(uint4*)(a_st + (soff) + A_HI)      = make_uint4(H_[0], H_[1], H_[2], H_[3]); \
    *(uint4*)(a_st + (soff) + A_HI + 16) = make_uint4(H_[4], H_[5], H_[6], H_[7]); \
    *(uint4*)(a_st + (soff) + A_LO)      = make_uint4(L_[0], L_[1], L_[2], L_[3]); \
    *(uint4*)(a_st + (soff) + A_LO + 16) = make_uint4(L_[4], L_[5], L_[6], L_[7]); }

#define ISSUE_B(soff, c) { \
    CPA(b_st0 + (soff) + B_HI, bhs0 + (c) * KCH); \
    CPA(b_st1 + (soff) + B_HI, bhs1 + (c) * KCH); \
    CPA(b_st0 + (soff) + B_LO, bls0 + (c) * KCH); \
    CPA(b_st1 + (soff) + B_LO, bls1 + (c) * KCH); }

    // prologue: chunks 0 and 1 into stages 0, 1
    ISSUE_B(0, 0); CPC();
    ISSUE_B(STG, 1); CPC();
    LOAD_A(0); STORE_A(0);
    LOAD_A(1); STORE_A(STG);

    for (int c = 0; c < NCHUNKS; c++) {
        int s = c % 3;
        uint32_t soff = (uint32_t)s * STG;
        CPW1();
        __syncthreads();
        int cn = c + 2;
        uint32_t snoff = (uint32_t)(cn % 3) * STG;
        if (cn < NCHUNKS) {
            LOAD_A(cn);
            ISSUE_B(snoff, cn);
        }
        CPC();
        // ---- mma on stage s ----
#pragma unroll
        for (int k16 = 0; k16 < 2; k16++) {
            uint32_t ah[2][4], al[2][4];
            ldsm4(ah[0], aA + soff + A_HI + k16 * 32);
            ldsm4(ah[1], aA + soff + A_HI + 16 * 80 + k16 * 32);
            ldsm4(al[0], aA + soff + A_LO + k16 * 32);
            ldsm4(al[1], aA + soff + A_LO + 16 * 80 + k16 * 32);
            uint32_t bh[4][4], bl[4][4];
#pragma unroll
            for (int g = 0; g < 4; g++) {
                ldsm4(bh[g], aB + soff + g * (16 * 80) + k16 * 32);
                ldsm4(bl[g], aB + soff + (B_LO - B_HI) + g * (16 * 80) + k16 * 32);
            }
#pragma unroll
            for (int mt = 0; mt < 2; mt++)
#pragma unroll
                for (int g = 0; g < 4; g++) {
                    mma16816(acc[mt][2 * g],     ah[mt], &bh[g][0]);
                    mma16816(acc[mt][2 * g],     ah[mt], &bl[g][0]);
                    mma16816(acc[mt][2 * g],     al[mt], &bh[g][0]);
                    mma16816(acc[mt][2 * g + 1], ah[mt], &bh[g][2]);
                    mma16816(acc[mt][2 * g + 1], ah[mt], &bl[g][2]);
                    mma16816(acc[mt][2 * g + 1], al[mt], &bh[g][2]);
                }
        }
        if (cn < NCHUNKS) STORE_A(snoff);
    }

    // ---- epilogue: LN correction + store to d_kf / d_vf ----
#pragma unroll
    for (int mt = 0; mt < 2; mt++) {
        long gr0 = row0 + m0 + mt * 16 + (l >> 2);
        long gr1 = gr0 + 8;
        float mean0 = d_stats[2 * gr0], rst0 = d_stats[2 * gr0 + 1];
        float mean1 = d_stats[2 * gr1], rst1 = d_stats[2 * gr1 + 1];
#pragma unroll
        for (int nt = 0; nt < 8; nt++) {
            int jl = N0 + n0w + nt * 8 + 2 * (l & 3);
            float wg0 = d_wgsum[jl], wg1 = d_wgsum[jl + 1];
            float wb0 = d_wb[jl],    wb1 = d_wb[jl + 1];
            float* outp; int col;
            if (jl < DH) { outp = d_kf; col = jl; } else { outp = d_vf; col = jl - DH; }
            float2 o0, o1;
            o0.x = rst0 * (acc[mt][nt][0] - mean0 * wg0) + wb0;
            o0.y = rst0 * (acc[mt][nt][1] - mean0 * wg1) + wb1;
            o1.x = rst1 * (acc[mt][nt][2] - mean1 * wg0) + wb0;
            o1.y = rst1 * (acc[mt][nt][3] - mean1 * wg1) + wb1;
            *(float2*)(outp + gr0 * 256 + col) = o0;
            *(float2*)(outp + gr1 * 256 + col) = o1;
        }
    }
}

// ---------------- kernel 4: copy prev_slots into working slots -------------
__global__ void copy_slots(const float* __restrict__ prev) {
    int i = blockIdx.x * 256 + threadIdx.x;
    d_slots[i] = prev[i];
}

// ---------------- kernel 5: zero accumulators ------------------------------
__global__ void zero_acc() {
    int i = blockIdx.x * 256 + threadIdx.x;
    d_U[i] = 0.f;
    if (i < B * KS) { d_S[i] = 0.f; d_msum[i] = 0.f; }
}

// ---------------- kernel 6: q = LN(slots) @ Wq^T ---------------------------
__global__ __launch_bounds__(256) void slot_q(const float* __restrict__ g_s,
                                              const float* __restrict__ b_s,
                                              const float* __restrict__ Wq) {
    int bk = blockIdx.x;
    int t = threadIdx.x;
    __shared__ float sn[DS];
    __shared__ float red[16];
    float x = d_slots[bk * DS + t];
    float s = x, s2 = x * x;
#pragma unroll
    for (int o = 16; o; o >>= 1) {
        s  += __shfl_xor_sync(~0u, s, o);
        s2 += __shfl_xor_sync(~0u, s2, o);
    }
    int w = t >> 5, l = t & 31;
    if (l == 0) { red[w] = s; red[8 + w] = s2; }
    __syncthreads();
    float ms = 0.f, q2 = 0.f;
    for (int i = 0; i < 8; i++) { ms += red[i]; q2 += red[8 + i]; }
    ms *= (1.f / DS);
    float var = q2 * (1.f / DS) - ms * ms;
    float rs = rsqrtf(var + LNEPS);
    sn[t] = (x - ms) * rs * g_s[t] + b_s[t];
    __syncthreads();
    const float4* w4 = (const float4*)(Wq + (long)t * DS);
    const float4* s4 = (const float4*)sn;
    float acc = 0.f;
#pragma unroll 8
    for (int i = 0; i < 64; i++) {
        float4 a = w4[i], c = s4[i];
        acc += a.x * c.x + a.y * c.y + a.z * c.z + a.w * c.w;
    }
    d_q[bk * DH + t] = acc;
}

// ---------------- kernel 7: attention + unnormalized update accumulation ---
__global__ __launch_bounds__(256) void attn_iter() {
    int b = blockIdx.y;
    int n0 = blockIdx.x * 256;
    int t = threadIdx.x, w = t >> 5, l = t & 31;
    __shared__ float qs[KS][DS];
#pragma unroll
    for (int k = 0; k < KS; k++) qs[k][t] = d_q[(b * KS + k) * DH + t];
    __syncthreads();

    float accU[KS][8];
    float sacc[KS];
#pragma unroll
    for (int k = 0; k < KS; k++) {
        sacc[k] = 0.f;
#pragma unroll
        for (int i = 0; i < 8; i++) accU[k][i] = 0.f;
    }

    for (int ni = 0; ni < 32; ni++) {
        int n = n0 + w * 32 + ni;
        long base = ((long)b * NTOK + n) * DH;
        float kf[8];
#pragma unroll
        for (int i = 0; i < 8; i++) kf[i] = d_kf[base + i * 32 + l];
        float lg[KS];
#pragma unroll
        for (int k = 0; k < KS; k++) lg[k] = 0.f;
#pragma unroll
        for (int i = 0; i < 8; i++) {
            float kv = kf[i];
            int d = i * 32 + l;
#pragma unroll
            for (int k = 0; k < KS; k++) lg[k] = fmaf(qs[k][d], kv, lg[k]);
        }
#pragma unroll
        for (int o = 16; o; o >>= 1)
#pragma unroll
            for (int k = 0; k < KS; k++) lg[k] += __shfl_xor_sync(~0u, lg[k], o);
#pragma unroll
        for (int k = 0; k < KS; k++) lg[k] *= ATT_SCALE;
        float mx = lg[0];
#pragma unroll
        for (int k = 1; k < KS; k++) mx = fmaxf(mx, lg[k]);
        float e[KS], se = 0.f;
#pragma unroll
        for (int k = 0; k < KS; k++) { e[k] = __expf(lg[k] - mx); se += e[k]; }
        float inv = 1.f / se;
        float vf[8];
#pragma unroll
        for (int i = 0; i < 8; i++) vf[i] = d_vf[base + i * 32 + l];
#pragma unroll
        for (int k = 0; k < KS; k++) {
            float a = e[k] * inv;
            sacc[k] += a;
#pragma unroll
            for (int i = 0; i < 8; i++) accU[k][i] = fmaf(a, vf[i], accU[k][i]);
        }
    }
#pragma unroll
    for (int k = 0; k < KS; k++) {
#pragma unroll
        for (int i = 0; i < 8; i++)
            atomicAdd(&d_U[(b * KS + k) * DS + i * 32 + l], accU[k][i]);
        if (l == 0) atomicAdd(&d_S[b * KS + k], sacc[k]);
    }
}

// ---------------- kernel 8: final attention (writes attn + mask sums) ------
__global__ __launch_bounds__(256) void attn_final(float* __restrict__ attn_out) {
    int b = blockIdx.y;
    int n0 = blockIdx.x * 256;
    int t = threadIdx.x, w = t >> 5, l = t & 31;
    __shared__ float qs[KS][DS];
    __shared__ float as_[KS][256];
#pragma unroll
    for (int k = 0; k < KS; k++) qs[k][t] = d_q[(b * KS + k) * DH + t];
    __syncthreads();

    float sacc[KS];
#pragma unroll
    for (int k = 0; k < KS; k++) sacc[k] = 0.f;

    for (int ni = 0; ni < 32; ni++) {
        int nl = w * 32 + ni;
        int n = n0 + nl;
        long base = ((long)b * NTOK + n) * DH;
        float kf[8];
#pragma unroll
        for (int i = 0; i < 8; i++) kf[i] = d_kf[base + i * 32 + l];
        float lg[KS];
#pragma unroll
        for (int k = 0; k < KS; k++) lg[k] = 0.f;
#pragma unroll
        for (int i = 0; i < 8; i++) {
            float kv = kf[i];
            int d = i * 32 + l;
#pragma unroll
            for (int k = 0; k < KS; k++) lg[k] = fmaf(qs[k][d], kv, lg[k]);
        }
#pragma unroll
        for (int o = 16; o; o >>= 1)
#pragma unroll
            for (int k = 0; k < KS; k++) lg[k] += __shfl_xor_sync(~0u, lg[k], o);
#pragma unroll
        for (int k = 0; k < KS; k++) lg[k] *= ATT_SCALE;
        float mx = lg[0];
#pragma unroll
        for (int k = 1; k < KS; k++) mx = fmaxf(mx, lg[k]);
        float e[KS], se = 0.f;
#pragma unroll
        for (int k = 0; k < KS; k++) { e[k] = __expf(lg[k] - mx); se += e[k]; }
        float inv = 1.f / se;
#pragma unroll
        for (int k = 0; k < KS; k++) {
            float a = e[k] * inv;
            sacc[k] += a;
            if (l == (unsigned)k) as_[k][nl] = a;
        }
    }
    __syncthreads();
#pragma unroll
    for (int k = 0; k < KS; k++)
        attn_out[((long)(b * KS + k)) * NTOK + n0 + t] = as_[k][t];
    if (l == 0)
#pragma unroll
        for (int k = 0; k < KS; k++) atomicAdd(&d_msum[b * KS + k], sacc[k]);
}

// ---------------- kernel 9: GRU + LN + MLP slot update ---------------------
__global__ __launch_bounds__(256) void slot_update(
    const float* __restrict__ W_ih, const float* __restrict__ W_hh,
    const float* __restrict__ b_ih, const float* __restrict__ b_hh,
    const float* __restrict__ g_m, const float* __restrict__ b_m,
    const float* __restrict__ W1, const float* __restrict__ b1,
    const float* __restrict__ W2, const float* __restrict__ b2) {
    int bk = blockIdx.x;
    int t = threadIdx.x;
    __shared__ float u[DS], so[DS], hn[DS], m1[DS];
    __shared__ float red[16];

    float Sv = d_S[bk] + EPSV;
    u[t]  = d_U[bk * DS + t] / Sv;
    so[t] = d_slots[bk * DS + t];
    __syncthreads();

    const float4* u4 = (const float4*)u;
    const float4* s4 = (const float4*)so;
    float gi[3], gh[3];
#pragma unroll
    for (int g = 0; g < 3; g++) {
        const float4* wi = (const float4*)(W_ih + (long)(g * DS + t) * DS);
        const float4* wh = (const float4*)(W_hh + (long)(g * DS + t) * DS);
        float ai = 0.f, ah = 0.f;
#pragma unroll 8
        for (int i = 0; i < 64; i++) {
            float4 a = wi[i], c = u4[i];
            ai += a.x * c.x + a.y * c.y + a.z * c.z + a.w * c.w;
            float4 d = wh[i], e = s4[i];
            ah += d.x * e.x + d.y * e.y + d.z * e.z + d.w * e.w;
        }
        gi[g] = ai + b_ih[g * DS + t];
        gh[g] = ah + b_hh[g * DS + t];
    }
    float r  = 1.f / (1.f + __expf(-(gi[0] + gh[0])));
    float z  = 1.f / (1.f + __expf(-(gi[1] + gh[1])));
    float nn = tanhf(gi[2] + r * gh[2]);
    float h  = (1.f - z) * nn + z * so[t];

    float s = h, s2 = h * h;
#pragma unroll
    for (int o = 16; o; o >>= 1) {
        s  += __shfl_xor_sync(~0u, s, o);
        s2 += __shfl_xor_sync(~0u, s2, o);
    }
    int w = t >> 5, l = t & 31;
    if (l == 0) { red[w] = s; red[8 + w] = s2; }
    __syncthreads();
    float ms = 0.f, q2 = 0.f;
    for (int i = 0; i < 8; i++) { ms += red[i]; q2 += red[8 + i]; }
    ms *= (1.f / DS);
    float var = q2 * (1.f / DS) - ms * ms;
    float rs = rsqrtf(var + LNEPS);
    hn[t] = (h - ms) * rs * g_m[t] + b_m[t];
    __syncthreads();

    {
        const float4* w1 = (const float4*)(W1 + (long)t * DS);
        const float4* x4 = (const float4*)hn;
        float a1 = 0.f;
#pragma unroll 8
        for (int i = 0; i < 64; i++) {
            float4 a = w1[i], c = x4[i];
            a1 += a.x * c.x + a.y * c.y + a.z * c.z + a.w * c.w;
        }
        m1[t] = fmaxf(a1 + b1[t], 0.f);
    }
    __syncthreads();
    {
        const float4* w2 = (const float4*)(W2 + (long)t * DS);
        const float4* x4 = (const float4*)m1;
        float a2 = 0.f;
#pragma unroll 8
        for (int i = 0; i < 64; i++) {
            float4 a = w2[i], c = x4[i];
            a2 += a.x * c.x + a.y * c.y + a.z * c.z + a.w * c.w;
        }
        d_slots[bk * DS + t] = h + a2 + b2[t];
    }
}

// ---------------- kernel 10: confidence blend ------------------------------
__global__ void blend(const float* __restrict__ prev, float* __restrict__ out) {
    int i = blockIdx.x * 256 + threadIdx.x;
    int bk = i >> 8;
    float mask = 1.f / (1.f + __expf(-d_msum[bk] * (1.f / NTOK)));
    out[i] = d_slots[i] * mask + prev[i] * (1.f - mask);
}

// ---------------- launch ---------------------------------------------------
extern "C" void kernel_launch(void* const* d_in, const int* in_sizes, int n_in,
                              void* d_out, int out_size) {
    const float* features  = (const float*)d_in[0];
    const float* prev      = (const float*)d_in[1];
    const float* g_in      = (const float*)d_in[2];
    const float* b_in      = (const float*)d_in[3];
    const float* g_s       = (const float*)d_in[4];
    const float* b_s       = (const float*)d_in[5];
    const float* g_m       = (const float*)d_in[6];
    const float* b_m       = (const float*)d_in[7];
    const float* Wq        = (const float*)d_in[8];
    const float* Wk        = (const float*)d_in[9];
    const float* Wv        = (const float*)d_in[10];
    const float* W_ih      = (const float*)d_in[11];
    const float* W_hh      = (const float*)d_in[12];
    const float* b_ih      = (const float*)d_in[13];
    const float* b_hh      = (const float*)d_in[14];
    const float* W1        = (const float*)d_in[15];
    const float* b1        = (const float*)d_in[16];
    const float* W2        = (const float*)d_in[17];
    const float* b2        = (const float*)d_in[18];

    float* out      = (float*)d_out;
    float* attn_out = out + B * KS * DS;

    cudaFuncSetAttribute(kv_gemm_mma, cudaFuncAttributeMaxDynamicSharedMemorySize, SMEM_GEMM);

    prep_weights<<<DH + DS, 256>>>(Wk, Wv, g_in, b_in);
    row_stats<<<B * NTOK / 8, 256>>>(features);
    kv_gemm_mma<<<dim3(4, B * NTOK / 128), 256, SMEM_GEMM>>>(features);
    copy_slots<<<B * KS * DS / 256, 256>>>(prev);

    for (int it = 0; it < NITER; it++) {
        zero_acc<<<B * KS * DS / 256, 256>>>();
        slot_q<<<B * KS, 256>>>(g_s, b_s, Wq);
        attn_iter<<<dim3(NTOK / 256, B), 256>>>();
        slot_update<<<B * KS, 256>>>(W_ih, W_hh, b_ih, b_hh, g_m, b_m, W1, b1, W2, b2);
    }
    zero_acc<<<B * KS * DS / 256, 256>>>();
    slot_q<<<B * KS, 256>>>(g_s, b_s, Wq);
    attn_final<<<dim3(NTOK / 256, B), 256>>>(attn_out);
    blend<<<B * KS * DS / 256, 256>>>(prev, out);
}